// round 5
// baseline (speedup 1.0000x reference)
#include <cuda_runtime.h>

// Problem constants (fixed by the reference):
// B=16, W=256, S=512, F=768, L=4, E=256, V=50000
#define BB 16
#define WW 256
#define SS 512
#define LL 4
#define NW (WW - 1)

#define NTASK 2048          // word-pairs
#define NCTA  456           // 152 SMs * 3 resident CTAs

// float4 strides inside layers[L, B, S, F/4=192]
#define LSTRIDE (BB * SS * 192)   // 1,572,864
#define BSTRIDE (SS * 192)        //    98,304

// Generic (slow) path: arbitrary span. Rare (w0==0 pairs, non-len-2 spans).
__device__ __noinline__ float4 span_mix_generic(
    const float4* __restrict__ layers4, int b, int ss, int se, int t,
    float w0, float w1, float w2, float w3, float g)
{
    float4 acc = make_float4(0.f, 0.f, 0.f, 0.f);
    const int len = se - ss;
    if (len <= 0) return acc;
    for (int s = ss; s < se; s++) {
        const float4* p = layers4 + (size_t)b * BSTRIDE + (size_t)s * 192 + t;
        float4 v0 = p[0 * LSTRIDE];
        float4 v1 = p[1 * LSTRIDE];
        float4 v2 = p[2 * LSTRIDE];
        float4 v3 = p[3 * LSTRIDE];
        acc.x += w0*v0.x + w1*v1.x + w2*v2.x + w3*v3.x;
        acc.y += w0*v0.y + w1*v1.y + w2*v2.y + w3*v3.y;
        acc.z += w0*v0.z + w1*v1.z + w2*v2.z + w3*v3.z;
        acc.w += w0*v0.w + w1*v1.w + w2*v2.w + w3*v3.w;
    }
    const float sc = g / (float)len;
    acc.x *= sc; acc.y *= sc; acc.z *= sc; acc.w *= sc;
    return acc;
}

// Persistent kernel: 456 CTAs x 192 threads grid-stride over 2048 word-pair
// tasks. Per iteration: 16 front-batched streaming LDG.128s (+2 emb gathers on
// threads 0..63), then the NEXT task's 6 scalar index loads (arrive during the
// data wait -> zero index stall next iteration), then compute + store.
__global__ __launch_bounds__(192, 3)
void bert_lexer_persist(
    const int* __restrict__ word_indices,   // [B, W]
    const int* __restrict__ span_starts,    // [B, W-1]
    const int* __restrict__ span_ends,      // [B, W-1]
    const float4* __restrict__ emb4,        // [V, E/4=64]
    const float4* __restrict__ layers4,     // [L, B, S, F/4=192]
    const float* __restrict__ layer_weights,// [L]
    const float* __restrict__ gamma,        // [1]
    float4* __restrict__ out4)              // [B, W, (E+F)/4=256]
{
    const int t = threadIdx.x;            // 0..191 -> float4 index within F
    const bool do_emb = (t < 64);

    // Softmax over the 4 layer weights: once per thread, before the loop.
    const float lw0 = __ldg(layer_weights + 0), lw1 = __ldg(layer_weights + 1);
    const float lw2 = __ldg(layer_weights + 2), lw3 = __ldg(layer_weights + 3);
    const float g   = __ldg(gamma);
    const float mx  = fmaxf(fmaxf(lw0, lw1), fmaxf(lw2, lw3));
    const float e0  = __expf(lw0 - mx), e1 = __expf(lw1 - mx);
    const float e2  = __expf(lw2 - mx), e3 = __expf(lw3 - mx);
    const float inv = 1.0f / (e0 + e1 + e2 + e3);
    const float sw0 = e0 * inv, sw1 = e1 * inv, sw2 = e2 * inv, sw3 = e3 * inv;
    // fast-path weights: softmax * gamma / len(=2)
    const float h0 = sw0 * g * 0.5f, h1 = sw1 * g * 0.5f;
    const float h2 = sw2 * g * 0.5f, h3 = sw3 * g * 0.5f;

    int task = blockIdx.x;
    if (task >= NTASK) return;

    // Prologue: indices for the first task.
    int bw0 = task << 1;
    int b   = bw0 >> 8;
    int w0  = bw0 & (WW - 1);
    int sb  = b * NW + w0;
    int idx0 = __ldg(word_indices + bw0);
    int idx1 = __ldg(word_indices + bw0 + 1);
    int ss1  = __ldg(span_starts + sb);
    int se1  = __ldg(span_ends   + sb);
    int ss0 = 0, se0 = 0;
    if (w0 > 0) { ss0 = __ldg(span_starts + sb - 1); se0 = __ldg(span_ends + sb - 1); }

    while (true) {
        const bool f0 = (w0 > 0) && (se0 - ss0 == 2);
        const bool f1 = (se1 - ss1 == 2);
        const bool fast = f0 && f1;

        // ---- issue streaming loads for the CURRENT task ----
        float4 x0, x1, x2, x3, x4, x5, x6, x7;
        float4 y0, y1, y2, y3, y4, y5, y6, y7;
        float4 ev0 = make_float4(0.f,0.f,0.f,0.f), ev1 = ev0;
        if (fast) {
            const float4* p0 = layers4 + (size_t)b * BSTRIDE + (size_t)ss0 * 192 + t;
            const float4* p1 = layers4 + (size_t)b * BSTRIDE + (size_t)ss1 * 192 + t;
            x0 = p0[0*LSTRIDE      ]; x1 = p0[0*LSTRIDE + 192];
            x2 = p0[1*LSTRIDE      ]; x3 = p0[1*LSTRIDE + 192];
            x4 = p0[2*LSTRIDE      ]; x5 = p0[2*LSTRIDE + 192];
            x6 = p0[3*LSTRIDE      ]; x7 = p0[3*LSTRIDE + 192];
            y0 = p1[0*LSTRIDE      ]; y1 = p1[0*LSTRIDE + 192];
            y2 = p1[1*LSTRIDE      ]; y3 = p1[1*LSTRIDE + 192];
            y4 = p1[2*LSTRIDE      ]; y5 = p1[2*LSTRIDE + 192];
            y6 = p1[3*LSTRIDE      ]; y7 = p1[3*LSTRIDE + 192];
        }
        if (do_emb) {
            ev0 = emb4[(size_t)idx0 * 64 + t];
            ev1 = emb4[(size_t)idx1 * 64 + t];
        }

        // ---- prefetch NEXT task's indices (hidden under the data wait) ----
        const int ntask = task + NCTA;
        const bool have_next = (ntask < NTASK);
        int nidx0 = 0, nidx1 = 0, nss0 = 0, nse0 = 0, nss1 = 0, nse1 = 0;
        int nb = 0, nw0 = 0, nbw0 = 0;
        if (have_next) {
            nbw0  = ntask << 1;
            nb    = nbw0 >> 8;
            nw0   = nbw0 & (WW - 1);
            const int nsb = nb * NW + nw0;
            nidx0 = __ldg(word_indices + nbw0);
            nidx1 = __ldg(word_indices + nbw0 + 1);
            nss1  = __ldg(span_starts + nsb);
            nse1  = __ldg(span_ends   + nsb);
            if (nw0 > 0) { nss0 = __ldg(span_starts + nsb - 1);
                           nse0 = __ldg(span_ends   + nsb - 1); }
        }

        // ---- compute + store the CURRENT task ----
        float4 acc0, acc1;
        if (fast) {
            acc0.x = h0*(x0.x+x1.x) + h1*(x2.x+x3.x) + h2*(x4.x+x5.x) + h3*(x6.x+x7.x);
            acc0.y = h0*(x0.y+x1.y) + h1*(x2.y+x3.y) + h2*(x4.y+x5.y) + h3*(x6.y+x7.y);
            acc0.z = h0*(x0.z+x1.z) + h1*(x2.z+x3.z) + h2*(x4.z+x5.z) + h3*(x6.z+x7.z);
            acc0.w = h0*(x0.w+x1.w) + h1*(x2.w+x3.w) + h2*(x4.w+x5.w) + h3*(x6.w+x7.w);
            acc1.x = h0*(y0.x+y1.x) + h1*(y2.x+y3.x) + h2*(y4.x+y5.x) + h3*(y6.x+y7.x);
            acc1.y = h0*(y0.y+y1.y) + h1*(y2.y+y3.y) + h2*(y4.y+y5.y) + h3*(y6.y+y7.y);
            acc1.z = h0*(y0.z+y1.z) + h1*(y2.z+y3.z) + h2*(y4.z+y5.z) + h3*(y6.z+y7.z);
            acc1.w = h0*(y0.w+y1.w) + h1*(y2.w+y3.w) + h2*(y4.w+y5.w) + h3*(y6.w+y7.w);
        } else {
            acc0 = make_float4(0.f,0.f,0.f,0.f);
            if (w0 > 0)
                acc0 = span_mix_generic(layers4, b, ss0, se0, t, sw0, sw1, sw2, sw3, g);
            acc1 = span_mix_generic(layers4, b, ss1, se1, t, sw0, sw1, sw2, sw3, g);
        }

        float4* __restrict__ o0 = out4 + (size_t)bw0 * 256;
        if (do_emb) { o0[t] = ev0; o0[256 + t] = ev1; }
        o0[64 + t]  = acc0;
        o0[320 + t] = acc1;

        if (!have_next) break;
        task = ntask; bw0 = nbw0; b = nb; w0 = nw0;
        idx0 = nidx0; idx1 = nidx1;
        ss0 = nss0; se0 = nse0; ss1 = nss1; se1 = nse1;
    }
}

extern "C" void kernel_launch(void* const* d_in, const int* in_sizes, int n_in,
                              void* d_out, int out_size)
{
    const int*    word_indices  = (const int*)   d_in[0];
    const int*    span_starts   = (const int*)   d_in[1];
    const int*    span_ends     = (const int*)   d_in[2];
    const float4* emb4          = (const float4*)d_in[3];
    const float4* layers4       = (const float4*)d_in[4];
    const float*  layer_weights = (const float*) d_in[5];
    const float*  gamma         = (const float*) d_in[6];
    float4*       out4          = (float4*)      d_out;

    (void)in_sizes; (void)n_in; (void)out_size;

    bert_lexer_persist<<<NCTA, 192>>>(word_indices, span_starts, span_ends,
                                      emb4, layers4, layer_weights, gamma, out4);
}

// round 6
// speedup vs baseline: 1.0986x; 1.0986x over previous
#include <cuda_runtime.h>

// Problem constants (fixed by the reference):
// B=16, W=256, S=512, F=768, L=4, E=256, V=50000
#define BB 16
#define WW 256
#define SS 512
#define LL 4
#define NW (WW - 1)

// float4 strides inside layers[L, B, S, F/4=192]
#define LSTRIDE (BB * SS * 192)   // 1,572,864
#define BSTRIDE (SS * 192)        //    98,304

// Streaming load: non-coherent, promote L2 fill granularity to 256B.
// All touched rows are 256B-aligned multiples, so this only coarsens DRAM
// bursts (fewer, larger requests) -- no wasted fetch.
__device__ __forceinline__ float4 ldg_stream(const float4* p) {
    float4 v;
    asm("ld.global.nc.L2::256B.v4.f32 {%0,%1,%2,%3}, [%4];"
        : "=f"(v.x), "=f"(v.y), "=f"(v.z), "=f"(v.w)
        : "l"(p));
    return v;
}

// Grid: one block per (b, w) pair = 4096 blocks, 192 threads.
// Every thread owns one float4 of the F=768 bert slice (8 front-batched
// streaming loads). Threads 0..63 additionally gather one float4 of the
// E=256 embedding row. No smem, no barriers.
__global__ __launch_bounds__(192, 5)
void bert_lexer_fused(
    const int* __restrict__ word_indices,   // [B, W]
    const int* __restrict__ span_starts,    // [B, W-1]
    const int* __restrict__ span_ends,      // [B, W-1]
    const float4* __restrict__ emb4,        // [V, E/4=64]
    const float4* __restrict__ layers4,     // [L, B, S, F/4=192]
    const float* __restrict__ layer_weights,// [L]
    const float* __restrict__ gamma,        // [1]
    float4* __restrict__ out4)              // [B, W, (E+F)/4=256]
{
    const int bw = blockIdx.x;        // b*W + w
    const int b  = bw >> 8;           // W = 256
    const int w  = bw & (WW - 1);
    const int t  = threadIdx.x;       // 0..191 -> float4 index within F

    float4* __restrict__ outrow = out4 + (size_t)bw * 256;

    // ---- embedding gather chain (threads 0..63), issued first ----
    float4 ev = make_float4(0.f, 0.f, 0.f, 0.f);
    const bool do_emb = (t < 64);
    if (do_emb) {
        const int idx = __ldg(word_indices + bw);
        ev = ldg_stream(emb4 + (size_t)idx * 64 + t);
    }

    // ---- bert slice: softmax-weighted layer mix averaged over the span ----
    float4 acc = make_float4(0.f, 0.f, 0.f, 0.f);
    if (w > 0) {
        const int si  = b * NW + (w - 1);
        const int ss  = __ldg(span_starts + si);
        const int se  = __ldg(span_ends   + si);
        const int len = se - ss;
        if (len > 0) {
            if (len == 2) {
                // Fast path (all spans in this dataset): 8 streaming loads
                // front-batched with nothing ahead of them.
                const float4* base = layers4 + (size_t)b * BSTRIDE + (size_t)ss * 192 + t;
                float4 a0 = ldg_stream(base + 0 * LSTRIDE      );
                float4 b0 = ldg_stream(base + 0 * LSTRIDE + 192);
                float4 a1 = ldg_stream(base + 1 * LSTRIDE      );
                float4 b1 = ldg_stream(base + 1 * LSTRIDE + 192);
                float4 a2 = ldg_stream(base + 2 * LSTRIDE      );
                float4 b2 = ldg_stream(base + 2 * LSTRIDE + 192);
                float4 a3 = ldg_stream(base + 3 * LSTRIDE      );
                float4 b3 = ldg_stream(base + 3 * LSTRIDE + 192);

                // Per-thread softmax (cached scalar loads, overlap the LDGs).
                float lw0 = __ldg(layer_weights + 0), lw1 = __ldg(layer_weights + 1);
                float lw2 = __ldg(layer_weights + 2), lw3 = __ldg(layer_weights + 3);
                float g   = __ldg(gamma);
                float m  = fmaxf(fmaxf(lw0, lw1), fmaxf(lw2, lw3));
                float e0 = __expf(lw0 - m), e1 = __expf(lw1 - m);
                float e2 = __expf(lw2 - m), e3 = __expf(lw3 - m);
                float sc = g * 0.5f / (e0 + e1 + e2 + e3);
                float w0 = e0 * sc, w1 = e1 * sc, w2 = e2 * sc, w3 = e3 * sc;

                acc.x = w0*(a0.x+b0.x) + w1*(a1.x+b1.x) + w2*(a2.x+b2.x) + w3*(a3.x+b3.x);
                acc.y = w0*(a0.y+b0.y) + w1*(a1.y+b1.y) + w2*(a2.y+b2.y) + w3*(a3.y+b3.y);
                acc.z = w0*(a0.z+b0.z) + w1*(a1.z+b1.z) + w2*(a2.z+b2.z) + w3*(a3.z+b3.z);
                acc.w = w0*(a0.w+b0.w) + w1*(a1.w+b1.w) + w2*(a2.w+b2.w) + w3*(a3.w+b3.w);
            } else {
                // Generic path (not hit with this dataset, kept for correctness).
                float lw0 = __ldg(layer_weights + 0), lw1 = __ldg(layer_weights + 1);
                float lw2 = __ldg(layer_weights + 2), lw3 = __ldg(layer_weights + 3);
                float g   = __ldg(gamma);
                float m  = fmaxf(fmaxf(lw0, lw1), fmaxf(lw2, lw3));
                float e0 = __expf(lw0 - m), e1 = __expf(lw1 - m);
                float e2 = __expf(lw2 - m), e3 = __expf(lw3 - m);
                float inv = 1.0f / (e0 + e1 + e2 + e3);
                float swt[LL] = {e0 * inv, e1 * inv, e2 * inv, e3 * inv};
                for (int s = ss; s < se; s++) {
                    #pragma unroll
                    for (int l = 0; l < LL; l++) {
                        float4 v = layers4[(size_t)l * LSTRIDE + (size_t)b * BSTRIDE
                                           + (size_t)s * 192 + t];
                        float wl = swt[l];
                        acc.x += wl * v.x; acc.y += wl * v.y;
                        acc.z += wl * v.z; acc.w += wl * v.w;
                    }
                }
                const float sc = g / (float)len;
                acc.x *= sc; acc.y *= sc; acc.z *= sc; acc.w *= sc;
            }
        }
    }

    // Evict-first streaming stores: output has no reuse, keep L2 for layers.
    if (do_emb) __stcs(outrow + t, ev);
    __stcs(outrow + 64 + t, acc);   // w==0 or empty span -> zeros (reference)
}

extern "C" void kernel_launch(void* const* d_in, const int* in_sizes, int n_in,
                              void* d_out, int out_size)
{
    const int*    word_indices  = (const int*)   d_in[0];
    const int*    span_starts   = (const int*)   d_in[1];
    const int*    span_ends     = (const int*)   d_in[2];
    const float4* emb4          = (const float4*)d_in[3];
    const float4* layers4       = (const float4*)d_in[4];
    const float*  layer_weights = (const float*) d_in[5];
    const float*  gamma         = (const float*) d_in[6];
    float4*       out4          = (float4*)      d_out;

    (void)in_sizes; (void)n_in; (void)out_size;

    bert_lexer_fused<<<BB * WW, 192>>>(word_indices, span_starts, span_ends,
                                       emb4, layers4, layer_weights, gamma, out4);
}